// round 15
// baseline (speedup 1.0000x reference)
#include <cuda_runtime.h>
#include <cstdint>

// ---------------------------------------------------------------------------
// CPC_80736795230858 : GRU(8192x256, hid 256) + CPC NCE scoring
// ---------------------------------------------------------------------------

#define SEQ      8192
#define DIMF     256
#define HID3     768
#define NEG_DIST 1365          // 8192 // 6
#define T_START  1024          // 8192 // 8
#define T_CNT    5791          // end(6815) - start(1024)
#define Z_ELEMS  (SEQ * DIMF)

typedef unsigned long long ull;

__device__ float g_xw[SEQ * HID3];
__device__ float g_dnorm[SEQ];
__device__ float g_pnce[T_CNT];
__device__ float g_pcorr[T_CNT];

// -------- helpers ----------------------------------------------------------
__device__ __forceinline__ void fma2(ull &acc, ull a, ull b) {
    asm("fma.rn.f32x2 %0, %1, %2, %0;" : "+l"(acc) : "l"(a), "l"(b));
}
__device__ __forceinline__ ull add2(ull a, ull b) {
    ull o; asm("add.rn.f32x2 %0, %1, %2;" : "=l"(o) : "l"(a), "l"(b)); return o;
}
__device__ __forceinline__ ull pack2(float lo, float hi) {
    ull o; asm("mov.b64 %0, {%1, %2};" : "=l"(o) : "f"(lo), "f"(hi)); return o;
}
__device__ __forceinline__ void unpack2(ull a, float &lo, float &hi) {
    asm("mov.b64 {%0,%1}, %2;" : "=f"(lo), "=f"(hi) : "l"(a));
}
__device__ __forceinline__ float psum2(ull a) {
    float lo, hi; unpack2(a, lo, hi); return lo + hi;
}
// HW tanh (sm_75+ MUFU): single op, lat ~16. max rel err ~2^-11.
__device__ __forceinline__ float tanh_hw(float x) {
    float y; asm("tanh.approx.f32 %0, %1;" : "=f"(y) : "f"(x)); return y;
}
__device__ __forceinline__ uint32_t mapa_u32(uint32_t addr, uint32_t rank) {
    uint32_t d;
    asm("mapa.shared::cluster.u32 %0, %1, %2;" : "=r"(d) : "r"(addr), "r"(rank));
    return d;
}
__device__ __forceinline__ void mbar_init(uint32_t mbar, uint32_t cnt) {
    asm volatile("mbarrier.init.shared.b64 [%0], %1;" :: "r"(mbar), "r"(cnt) : "memory");
}
__device__ __forceinline__ void mbar_arrive_expect_tx(uint32_t mbar, uint32_t bytes) {
    asm volatile("mbarrier.arrive.expect_tx.shared::cta.b64 _, [%0], %1;"
                 :: "r"(mbar), "r"(bytes) : "memory");
}
__device__ __forceinline__ void st_async_f32(uint32_t raddr, float v, uint32_t rmbar) {
    asm volatile("st.async.shared::cluster.mbarrier::complete_tx::bytes.f32 [%0], %1, [%2];"
                 :: "r"(raddr), "f"(v), "r"(rmbar) : "memory");
}
__device__ __forceinline__ void st_async_b64(uint32_t raddr, ull v, uint32_t rmbar) {
    asm volatile("st.async.shared::cluster.mbarrier::complete_tx::bytes.b64 [%0], %1, [%2];"
                 :: "r"(raddr), "l"(v), "r"(rmbar) : "memory");
}
__device__ __forceinline__ void wait_parity_cluster(uint32_t mbar, uint32_t parity) {
    asm volatile(
        "{\n\t"
        ".reg .pred P;\n\t"
        "WL%=:\n\t"
        "mbarrier.try_wait.parity.acquire.cluster.shared::cta.b64 P, [%0], %1, 0x989680;\n\t"
        "@P bra.uni WD%=;\n\t"
        "bra.uni WL%=;\n\t"
        "WD%=:\n\t"
        "}"
        :: "r"(mbar), "r"(parity) : "memory");
}

// ---------------------------------------------------------------------------
// Kernel 1: xW = data @ Wih^T + bih  (M=8192, N=768, K=256), f32x2 inner loop
// ---------------------------------------------------------------------------
__global__ __launch_bounds__(256) void cpc_xw_gemm(
    const float* __restrict__ A, const float* __restrict__ B,
    const float* __restrict__ bias)
{
    __shared__ float sA[16][66];     // stride 66 (even) -> 8B-aligned pairs
    __shared__ float sB[16][66];
    const int bx = blockIdx.x, by = blockIdx.y;
    const int tid = threadIdx.x;
    const int tx = tid & 15, ty = tid >> 4;

    ull acc2[4][2];
#pragma unroll
    for (int i = 0; i < 4; i++) { acc2[i][0] = 0; acc2[i][1] = 0; }

    const int lrow = tid >> 2;
    const int lkc  = (tid & 3) * 4;

    for (int k0 = 0; k0 < DIMF; k0 += 16) {
        float4 va = *(const float4*)(A + (by * 64 + lrow) * DIMF + k0 + lkc);
        float4 vb = *(const float4*)(B + (bx * 64 + lrow) * DIMF + k0 + lkc);
        sA[lkc + 0][lrow] = va.x; sA[lkc + 1][lrow] = va.y;
        sA[lkc + 2][lrow] = va.z; sA[lkc + 3][lrow] = va.w;
        sB[lkc + 0][lrow] = vb.x; sB[lkc + 1][lrow] = vb.y;
        sB[lkc + 2][lrow] = vb.z; sB[lkc + 3][lrow] = vb.w;
        __syncthreads();
#pragma unroll
        for (int kk = 0; kk < 16; kk++) {
            ull b2[2];
            b2[0] = *(const ull*)&sB[kk][tx * 4];
            b2[1] = *(const ull*)&sB[kk][tx * 4 + 2];
#pragma unroll
            for (int i = 0; i < 4; i++) {
                float av = sA[kk][ty * 4 + i];
                ull a2 = pack2(av, av);
                fma2(acc2[i][0], a2, b2[0]);
                fma2(acc2[i][1], a2, b2[1]);
            }
        }
        __syncthreads();
    }
#pragma unroll
    for (int i = 0; i < 4; i++) {
        int m = by * 64 + ty * 4 + i;
        float c0, c1, c2, c3;
        unpack2(acc2[i][0], c0, c1);
        unpack2(acc2[i][1], c2, c3);
        int n = bx * 64 + tx * 4;
        g_xw[m * HID3 + n + 0] = c0 + bias[n + 0];
        g_xw[m * HID3 + n + 1] = c1 + bias[n + 1];
        g_xw[m * HID3 + n + 2] = c2 + bias[n + 2];
        g_xw[m * HID3 + n + 3] = c3 + bias[n + 3];
    }
}

// ---------------------------------------------------------------------------
// Kernel 2: row norms of data
// ---------------------------------------------------------------------------
__global__ __launch_bounds__(256) void cpc_norms(const float* __restrict__ data)
{
    int row = blockIdx.x * 8 + (threadIdx.x >> 5);
    int l = threadIdx.x & 31;
    const float4* p = (const float4*)(data + row * DIMF);
    float s = 0.0f;
#pragma unroll
    for (int i = l; i < 64; i += 32) {
        float4 v = p[i];
        s += v.x * v.x + v.y * v.y + v.z * v.z + v.w * v.w;
    }
#pragma unroll
    for (int off = 16; off > 0; off >>= 1)
        s += __shfl_xor_sync(0xffffffffu, s, off);
    if (l == 0) g_dnorm[row] = fmaxf(sqrtf(s), 1e-8f);
}

// ---------------------------------------------------------------------------
// Kernel 2b: ONE dummy — capture slot = 4th user launch => cpc_gru
// ---------------------------------------------------------------------------
__global__ void cpc_dummy() {}

// ---------------------------------------------------------------------------
// Kernel 3: GRU recurrence — 8-CTA cluster, Whh register-resident,
// 512 threads: SPLIT-GATE matvec.
//   warps 0-7  : k-chunk w,    gates r,z  (32 fma2 per lane)
//   warps 8-15 : k-chunk w-8,  gate  n    (16 fma2 per lane, bhh_n seeded)
// Both warps of a chunk pair sleep on the same per-source mbar; the last-
// arriving chunk's critical matvec is 32 fma2 instead of 48.
// Warp0 tail identical to R14: HW-tanh gates, xr/xz seeded into the rz
// accumulator, hprev register, plain f32 sends.
// Protocol: arm-after-wait by warp c (c<8) lane0 only — safe: phase N+1
// cannot complete before warp c+8 passes phase N (completion requires next
// sends -> gates -> __syncthreads -> c+8's STS -> c+8 past its wait).
// Final-step sends skipped; trailing cluster barrier.
// ---------------------------------------------------------------------------
struct GruStepState {
    float xr, xz, xn;      // xr,xz have bhh folded; xn is raw xW value
};

__global__ void __cluster_dims__(8, 1, 1) __launch_bounds__(512, 1)
cpc_gru(const float* __restrict__ Whh,
        const float* __restrict__ bhh,
        float* __restrict__ z)
{
    __shared__ float hbuf[2][256];
    __shared__ ull   part_rz[8][32];       // packed (r,z) partials [chunk][lane]
    __shared__ float part_n[8][32];
    __shared__ alignas(16) ull mbar[16];   // [buf*8 + src]

    const int tid = threadIdx.x;
    const int w = tid >> 5, l = tid & 31;
    const int c = w & 7;                   // k-chunk id
    const bool is_rz = (w < 8);
    uint32_t rank;
    asm("mov.u32 %0, %%cluster_ctarank;" : "=r"(rank));
    const int j = (int)rank * 32 + l;      // output hidden index (per lane)

    // ---- weights: r,z rows on warps 0-7; n row on warps 8-15 ----
    ull wr[16], wz[16], wn[16];
    if (is_rz) {
        const ull* pr = (const ull*)(Whh + (j      ) * DIMF + 32 * c);
        const ull* pz = (const ull*)(Whh + (256 + j) * DIMF + 32 * c);
#pragma unroll
        for (int i = 0; i < 16; i++) { wr[i] = pr[i]; wz[i] = pz[i]; }
    } else {
        const ull* pn = (const ull*)(Whh + (512 + j) * DIMF + 32 * c);
#pragma unroll
        for (int i = 0; i < 16; i++) wn[i] = pn[i];
    }

    const uint32_t hb = (uint32_t)__cvta_generic_to_shared(&hbuf[0][0]);
    const uint32_t mb = (uint32_t)__cvta_generic_to_shared(&mbar[0]);

    float bh_r = 0, bh_z = 0, bh_n = 0;
    GruStepState bufA = {0,0,0}, bufB = {0,0,0};
    float hprev = 0.0f;                    // warp0: h(t-1)[j] register copy
    uint32_t peer_h[8], peer_m[8];
    if (w == 0) {
        bh_r = bhh[j]; bh_z = bhh[256 + j];
        bufA.xr = g_xw[j]            + bh_r;    // t = 0
        bufA.xz = g_xw[256 + j]      + bh_z;
        bufA.xn = g_xw[512 + j];                // raw (bh_n seeded by warp 8)
        bufB.xr = g_xw[HID3 + j]       + bh_r;  // t = 1
        bufB.xz = g_xw[HID3 + 256 + j] + bh_z;
        bufB.xn = g_xw[HID3 + 512 + j];
#pragma unroll
        for (int r = 0; r < 8; r++) {
            peer_h[r] = mapa_u32(hb, (uint32_t)r);
            peer_m[r] = mapa_u32(mb, (uint32_t)r);
        }
    }
    if (w == 8) bh_n = bhh[512 + j];       // n-chunk-0 warp seeds bhh_n
    if (tid < 16) {
        mbar_init(mb + tid * 8, 1);
    }
    if (tid < 512) {
        ((float*)hbuf)[tid] = 0.0f;        // zero both buffers (512 floats)
    }
    __syncthreads();
    // Arm BOTH buffers' mbars before any cluster traffic is possible.
    if (tid < 16) mbar_arrive_expect_tx(mb + tid * 8, 128u);
    __syncthreads();
    asm volatile("barrier.cluster.arrive.aligned;" ::: "memory");
    asm volatile("barrier.cluster.wait.aligned;"   ::: "memory");

    // pre-seed buffer 0 with h(-1) = 0
    if (w == 0 && (l & 1) == 0) {
        const uint32_t off = (uint32_t)(j * 4);            // buf 0
        const uint32_t mof = (uint32_t)(rank * 8);         // mbar[0][rank]
#pragma unroll
        for (int r = 0; r < 8; r++)
            st_async_b64(peer_h[r] + off, 0ull, peer_m[r] + mof);
    }

    uint32_t php[2] = {0u, 0u};    // this warp's parity for mbar[buf][c]

#pragma unroll 1
    for (int t = 0; t < SEQ; t += 2) {
#pragma unroll
        for (int half = 0; half < 2; half++) {
            const int tc = t + half;
            const int p = tc & 1;
            const int q = p ^ 1;
            GruStepState &cur = half ? bufB : bufA;   // also the t+2 refill slot

            // ---- wait for my source chunk (both warps of the pair) ----
            wait_parity_cluster(mb + (p * 8 + c) * 8, php[p]);
            php[p] ^= 1u;
            // re-arm by the rz warp's lane0 only (one arrive per phase)
            if (is_rz && l == 0) mbar_arrive_expect_tx(mb + (p * 8 + c) * 8, 128u);

            // ---- matvec over my k-chunk of hbuf[p] ----
            const ull* h2 = (const ull*)(&hbuf[p][32 * c]);
            if (is_rz) {
                ull ar = 0, az = 0;
                if (w == 0) {                 // seed gate inputs (bias-folded)
                    ar = pack2(cur.xr, 0.0f);
                    az = pack2(cur.xz, 0.0f);
                }
#pragma unroll
                for (int i = 0; i < 16; i++) {
                    ull hv = h2[i];
                    fma2(ar, wr[i], hv);
                    fma2(az, wz[i], hv);
                }
                part_rz[c][l] = pack2(psum2(ar), psum2(az));
            } else {
                ull an = 0;
                if (w == 8) an = pack2(bh_n, 0.0f);   // seed bhh_n once
#pragma unroll
                for (int i = 0; i < 16; i++) {
                    fma2(an, wn[i], h2[i]);
                }
                part_n[c][l] = psum2(an);
            }
            __syncthreads();

            if (w == 0) {
                const float xn = cur.xn;
                // refill with t+2 (LDGs hide under the reduce + gates)
                {
                    int tn = tc + 2 < SEQ ? tc + 2 : tc;
                    const float* xwp = g_xw + tn * HID3;
                    cur.xr = xwp[j]       + bh_r;
                    cur.xz = xwp[256 + j] + bh_z;
                    cur.xn = xwp[512 + j];
                }
                // packed (r,z) reduce + scalar n reduce
                ull s01 = add2(part_rz[0][l], part_rz[1][l]);
                ull s23 = add2(part_rz[2][l], part_rz[3][l]);
                ull s45 = add2(part_rz[4][l], part_rz[5][l]);
                ull s67 = add2(part_rz[6][l], part_rz[7][l]);
                ull srz = add2(add2(s01, s23), add2(s45, s67));
                float hr, hz; unpack2(srz, hr, hz);   // include xr/xz already
                float hn = ((part_n[0][l] + part_n[1][l]) + (part_n[2][l] + part_n[3][l]))
                         + ((part_n[4][l] + part_n[5][l]) + (part_n[6][l] + part_n[7][l]));
                // HW tanh gates: sigm(x) = 0.5*tanh(0.5x) + 0.5
                float rg = fmaf(tanh_hw(0.5f * hr), 0.5f, 0.5f);
                float zg = fmaf(tanh_hw(0.5f * hz), 0.5f, 0.5f);
                float ng = tanh_hw(fmaf(rg, hn, xn));   // hn includes bh_n
                float hnew = fmaf(zg, hprev - ng, ng);
                hprev = hnew;

                // sends: plain f32 from every lane. Skip on the final step.
                if ((tc + 1) < SEQ) {
                    const uint32_t off = (uint32_t)((q * 256 + j) * 4);
                    const uint32_t mof = (uint32_t)((q * 8 + (int)rank) * 8);
#pragma unroll
                    for (int r = 0; r < 8; r++)
                        st_async_f32(peer_h[r] + off, hnew, peer_m[r] + mof);
                }
                z[tc * DIMF + j] = hnew;
            }
        }
    }
    // exit hygiene: no CTA leaves while any peer could still be running
    asm volatile("barrier.cluster.arrive.aligned;" ::: "memory");
    asm volatile("barrier.cluster.wait.aligned;"   ::: "memory");
}

// ---------------------------------------------------------------------------
// Kernel 4: CPC scoring — one block per t
// ---------------------------------------------------------------------------
__global__ __launch_bounds__(256) void cpc_score(
    const float* __restrict__ z, const float* __restrict__ data)
{
    const int bt = blockIdx.x;
    const int t = T_START + bt;
    __shared__ float c[256];
    __shared__ float sims[40];
    __shared__ float wsum[8];
    __shared__ float cn;
    __shared__ float resN[4], resC[4];

    const int tid = threadIdx.x;
    const int w = tid >> 5, l = tid & 31;

    float v = z[t * DIMF + tid];
    c[tid] = v;
    float s = v * v;
#pragma unroll
    for (int off = 16; off > 0; off >>= 1)
        s += __shfl_xor_sync(0xffffffffu, s, off);
    if (l == 0) wsum[w] = s;
    __syncthreads();
    if (tid == 0) {
        float tot = 0;
#pragma unroll
        for (int qq = 0; qq < 8; qq++) tot += wsum[qq];
        cn = fmaxf(sqrtf(tot), 1e-8f);
    }
    __syncthreads();

#pragma unroll
    for (int d = 0; d < 5; d++) {
        int id = w * 5 + d;
        int sp = id / 10 + 1;
        int n = id % 10;
        int row = t + sp + (n ? (NEG_DIST + n - 1) : 0);
        const float* x = data + row * DIMF;
        float dot = 0.0f;
#pragma unroll
        for (int i = 0; i < 8; i++) dot += x[l + 32 * i] * c[l + 32 * i];
#pragma unroll
        for (int off = 16; off > 0; off >>= 1)
            dot += __shfl_xor_sync(0xffffffffu, dot, off);
        if (l == 0) sims[id] = dot / (g_dnorm[row] * cn);
    }
    __syncthreads();

    if (tid < 4) {
        const float* sm = sims + tid * 10;
        float s0 = sm[0];
        float mx = sm[1];
#pragma unroll
        for (int n = 2; n < 10; n++) mx = fmaxf(mx, sm[n]);
        float M = fmaxf(mx, s0);
        float se = 0.0f;
#pragma unroll
        for (int n = 0; n < 10; n++) se += __expf(sm[n] - M);
        resN[tid] = s0 - (M + __logf(se));
        resC[tid] = (s0 >= mx) ? 1.0f : 0.0f;
    }
    __syncthreads();
    if (tid == 0) {
        g_pnce[bt]  = resN[0] + resN[1] + resN[2] + resN[3];
        g_pcorr[bt] = resC[0] + resC[1] + resC[2] + resC[3];
    }
}

// ---------------------------------------------------------------------------
// Kernel 5: final deterministic reduction -> nce, acc
// ---------------------------------------------------------------------------
__global__ __launch_bounds__(256) void cpc_final(float* __restrict__ out)
{
    __shared__ double sN[256], sC[256];
    const int tid = threadIdx.x;
    double a = 0.0, b = 0.0;
    for (int i = tid; i < T_CNT; i += 256) { a += (double)g_pnce[i]; b += (double)g_pcorr[i]; }
    sN[tid] = a; sC[tid] = b;
    __syncthreads();
    for (int s = 128; s > 0; s >>= 1) {
        if (tid < s) { sN[tid] += sN[tid + s]; sC[tid] += sC[tid + s]; }
        __syncthreads();
    }
    if (tid == 0) {
        const double denom = (double)T_CNT * 4.0;
        out[Z_ELEMS]     = (float)(-sN[0] / denom);
        out[Z_ELEMS + 1] = (float)( sC[0] / denom);
    }
}

// ---------------------------------------------------------------------------
extern "C" void kernel_launch(void* const* d_in, const int* in_sizes, int n_in,
                              void* d_out, int out_size)
{
    const float* data = (const float*)d_in[0];
    const float* Wih  = (const float*)d_in[1];
    const float* Whh  = (const float*)d_in[2];
    const float* bih  = (const float*)d_in[3];
    const float* bhh  = (const float*)d_in[4];
    float* out = (float*)d_out;

    dim3 gg(12, 128);
    cpc_xw_gemm<<<gg, 256>>>(data, Wih, bih);   // user launch 1
    cpc_norms<<<SEQ / 8, 256>>>(data);          // user launch 2
    cpc_dummy<<<1, 32>>>();                     // user launch 3
    cpc_gru<<<8, 512>>>(Whh, bhh, out);         // user launch 4 <- capture slot
    cpc_score<<<T_CNT, 256>>>(out, data);
    cpc_final<<<1, 256>>>(out);
}

// round 16
// speedup vs baseline: 1.4250x; 1.4250x over previous
#include <cuda_runtime.h>
#include <cstdint>

// ---------------------------------------------------------------------------
// CPC_80736795230858 : GRU(8192x256, hid 256) + CPC NCE scoring
// ---------------------------------------------------------------------------

#define SEQ      8192
#define DIMF     256
#define HID3     768
#define NEG_DIST 1365          // 8192 // 6
#define T_START  1024          // 8192 // 8
#define T_CNT    5791          // end(6815) - start(1024)
#define Z_ELEMS  (SEQ * DIMF)

typedef unsigned long long ull;

__device__ float g_xw[SEQ * HID3];
__device__ float g_dnorm[SEQ];
__device__ float g_pnce[T_CNT];
__device__ float g_pcorr[T_CNT];

// -------- helpers ----------------------------------------------------------
__device__ __forceinline__ void fma2(ull &acc, ull a, ull b) {
    asm("fma.rn.f32x2 %0, %1, %2, %0;" : "+l"(acc) : "l"(a), "l"(b));
}
__device__ __forceinline__ ull add2(ull a, ull b) {
    ull o; asm("add.rn.f32x2 %0, %1, %2;" : "=l"(o) : "l"(a), "l"(b)); return o;
}
__device__ __forceinline__ ull pack2(float lo, float hi) {
    ull o; asm("mov.b64 %0, {%1, %2};" : "=l"(o) : "f"(lo), "f"(hi)); return o;
}
__device__ __forceinline__ void unpack2(ull a, float &lo, float &hi) {
    asm("mov.b64 {%0,%1}, %2;" : "=f"(lo), "=f"(hi) : "l"(a));
}
__device__ __forceinline__ float psum2(ull a) {
    float lo, hi; unpack2(a, lo, hi); return lo + hi;
}
// HW tanh (sm_75+ MUFU): single op, lat ~16. max rel err ~2^-11.
__device__ __forceinline__ float tanh_hw(float x) {
    float y; asm("tanh.approx.f32 %0, %1;" : "=f"(y) : "f"(x)); return y;
}
__device__ __forceinline__ uint32_t mapa_u32(uint32_t addr, uint32_t rank) {
    uint32_t d;
    asm("mapa.shared::cluster.u32 %0, %1, %2;" : "=r"(d) : "r"(addr), "r"(rank));
    return d;
}
__device__ __forceinline__ void mbar_init(uint32_t mbar, uint32_t cnt) {
    asm volatile("mbarrier.init.shared.b64 [%0], %1;" :: "r"(mbar), "r"(cnt) : "memory");
}
__device__ __forceinline__ void mbar_arrive_expect_tx(uint32_t mbar, uint32_t bytes) {
    asm volatile("mbarrier.arrive.expect_tx.shared::cta.b64 _, [%0], %1;"
                 :: "r"(mbar), "r"(bytes) : "memory");
}
__device__ __forceinline__ void st_async_f32(uint32_t raddr, float v, uint32_t rmbar) {
    asm volatile("st.async.shared::cluster.mbarrier::complete_tx::bytes.f32 [%0], %1, [%2];"
                 :: "r"(raddr), "f"(v), "r"(rmbar) : "memory");
}
__device__ __forceinline__ void st_async_b64(uint32_t raddr, ull v, uint32_t rmbar) {
    asm volatile("st.async.shared::cluster.mbarrier::complete_tx::bytes.b64 [%0], %1, [%2];"
                 :: "r"(raddr), "l"(v), "r"(rmbar) : "memory");
}
__device__ __forceinline__ void wait_parity_cluster(uint32_t mbar, uint32_t parity) {
    asm volatile(
        "{\n\t"
        ".reg .pred P;\n\t"
        "WL%=:\n\t"
        "mbarrier.try_wait.parity.acquire.cluster.shared::cta.b64 P, [%0], %1, 0x989680;\n\t"
        "@P bra.uni WD%=;\n\t"
        "bra.uni WL%=;\n\t"
        "WD%=:\n\t"
        "}"
        :: "r"(mbar), "r"(parity) : "memory");
}

// ---------------------------------------------------------------------------
// Kernel 1: xW = data @ Wih^T + bih  (M=8192, N=768, K=256), f32x2 inner loop
// ---------------------------------------------------------------------------
__global__ __launch_bounds__(256) void cpc_xw_gemm(
    const float* __restrict__ A, const float* __restrict__ B,
    const float* __restrict__ bias)
{
    __shared__ float sA[16][66];     // stride 66 (even) -> 8B-aligned pairs
    __shared__ float sB[16][66];
    const int bx = blockIdx.x, by = blockIdx.y;
    const int tid = threadIdx.x;
    const int tx = tid & 15, ty = tid >> 4;

    ull acc2[4][2];
#pragma unroll
    for (int i = 0; i < 4; i++) { acc2[i][0] = 0; acc2[i][1] = 0; }

    const int lrow = tid >> 2;
    const int lkc  = (tid & 3) * 4;

    for (int k0 = 0; k0 < DIMF; k0 += 16) {
        float4 va = *(const float4*)(A + (by * 64 + lrow) * DIMF + k0 + lkc);
        float4 vb = *(const float4*)(B + (bx * 64 + lrow) * DIMF + k0 + lkc);
        sA[lkc + 0][lrow] = va.x; sA[lkc + 1][lrow] = va.y;
        sA[lkc + 2][lrow] = va.z; sA[lkc + 3][lrow] = va.w;
        sB[lkc + 0][lrow] = vb.x; sB[lkc + 1][lrow] = vb.y;
        sB[lkc + 2][lrow] = vb.z; sB[lkc + 3][lrow] = vb.w;
        __syncthreads();
#pragma unroll
        for (int kk = 0; kk < 16; kk++) {
            ull b2[2];
            b2[0] = *(const ull*)&sB[kk][tx * 4];
            b2[1] = *(const ull*)&sB[kk][tx * 4 + 2];
#pragma unroll
            for (int i = 0; i < 4; i++) {
                float av = sA[kk][ty * 4 + i];
                ull a2 = pack2(av, av);
                fma2(acc2[i][0], a2, b2[0]);
                fma2(acc2[i][1], a2, b2[1]);
            }
        }
        __syncthreads();
    }
#pragma unroll
    for (int i = 0; i < 4; i++) {
        int m = by * 64 + ty * 4 + i;
        float c0, c1, c2, c3;
        unpack2(acc2[i][0], c0, c1);
        unpack2(acc2[i][1], c2, c3);
        int n = bx * 64 + tx * 4;
        g_xw[m * HID3 + n + 0] = c0 + bias[n + 0];
        g_xw[m * HID3 + n + 1] = c1 + bias[n + 1];
        g_xw[m * HID3 + n + 2] = c2 + bias[n + 2];
        g_xw[m * HID3 + n + 3] = c3 + bias[n + 3];
    }
}

// ---------------------------------------------------------------------------
// Kernel 2: row norms of data
// ---------------------------------------------------------------------------
__global__ __launch_bounds__(256) void cpc_norms(const float* __restrict__ data)
{
    int row = blockIdx.x * 8 + (threadIdx.x >> 5);
    int l = threadIdx.x & 31;
    const float4* p = (const float4*)(data + row * DIMF);
    float s = 0.0f;
#pragma unroll
    for (int i = l; i < 64; i += 32) {
        float4 v = p[i];
        s += v.x * v.x + v.y * v.y + v.z * v.z + v.w * v.w;
    }
#pragma unroll
    for (int off = 16; off > 0; off >>= 1)
        s += __shfl_xor_sync(0xffffffffu, s, off);
    if (l == 0) g_dnorm[row] = fmaxf(sqrtf(s), 1e-8f);
}

// ---------------------------------------------------------------------------
// Kernel 2b: ONE dummy — capture slot = 4th user launch => cpc_gru
// ---------------------------------------------------------------------------
__global__ void cpc_dummy() {}

// ---------------------------------------------------------------------------
// Kernel 3: GRU recurrence — 8-CTA cluster, Whh register-resident,
// per-source mbarriers mbar[buf][src] (expect_tx = 128B); warp0-only tail.
// R14 architecture (confirmed optimum of this family) + R16 micro-opt:
//  * warp0 keeps its own chunk-0 partials in REGISTERS (no STS/LDS round
//    trip); reduce uses the register in the same tree slot => bit-identical.
//  * HW tanh.approx gates; xr/xz/bh_n seeded into matvec accumulators.
//  * hprev register; plain f32 sends.
// Protocol invariants (R9): arm-after-wait; final-step sends skipped;
// trailing cluster barrier.
// ---------------------------------------------------------------------------
struct GruStepState {
    float xr, xz, xn;      // xr,xz have bhh folded; xn is raw xW value
};

__global__ void __cluster_dims__(8, 1, 1) __launch_bounds__(256, 1)
cpc_gru(const float* __restrict__ Whh,
        const float* __restrict__ bhh,
        float* __restrict__ z)
{
    __shared__ float hbuf[2][256];
    __shared__ ull   part_rz[8][32];       // packed (r,z) partials (chunks 1-7)
    __shared__ float part_n[8][32];
    __shared__ alignas(16) ull mbar[16];   // [buf*8 + src]

    const int tid = threadIdx.x;
    const int w = tid >> 5, l = tid & 31;
    uint32_t rank;
    asm("mov.u32 %0, %%cluster_ctarank;" : "=r"(rank));
    const int j = (int)rank * 32 + l;

    ull wr[16], wz[16], wn[16];
    {
        const ull* pr = (const ull*)(Whh + (j      ) * DIMF + 32 * w);
        const ull* pz = (const ull*)(Whh + (256 + j) * DIMF + 32 * w);
        const ull* pn = (const ull*)(Whh + (512 + j) * DIMF + 32 * w);
#pragma unroll
        for (int i = 0; i < 16; i++) { wr[i] = pr[i]; wz[i] = pz[i]; wn[i] = pn[i]; }
    }

    const uint32_t hb = (uint32_t)__cvta_generic_to_shared(&hbuf[0][0]);
    const uint32_t mb = (uint32_t)__cvta_generic_to_shared(&mbar[0]);

    float bh_r = 0, bh_z = 0, bh_n = 0;
    GruStepState bufA = {0,0,0}, bufB = {0,0,0};
    float hprev = 0.0f;                    // warp0: h(t-1)[j] register copy
    uint32_t peer_h[8], peer_m[8];
    if (w == 0) {
        bh_r = bhh[j]; bh_z = bhh[256 + j]; bh_n = bhh[512 + j];
        bufA.xr = g_xw[j]            + bh_r;    // t = 0
        bufA.xz = g_xw[256 + j]      + bh_z;
        bufA.xn = g_xw[512 + j];                // raw (bh_n NOT folded)
        bufB.xr = g_xw[HID3 + j]       + bh_r;  // t = 1
        bufB.xz = g_xw[HID3 + 256 + j] + bh_z;
        bufB.xn = g_xw[HID3 + 512 + j];
#pragma unroll
        for (int r = 0; r < 8; r++) {
            peer_h[r] = mapa_u32(hb, (uint32_t)r);
            peer_m[r] = mapa_u32(mb, (uint32_t)r);
        }
    }
    if (tid < 16) {
        mbar_init(mb + tid * 8, 1);
    }
    ((float*)hbuf)[tid] = 0.0f;
    ((float*)hbuf)[tid + 256] = 0.0f;
    __syncthreads();
    // Arm BOTH buffers' mbars before any cluster traffic is possible.
    if (tid < 16) mbar_arrive_expect_tx(mb + tid * 8, 128u);
    __syncthreads();
    asm volatile("barrier.cluster.arrive.aligned;" ::: "memory");
    asm volatile("barrier.cluster.wait.aligned;"   ::: "memory");

    // pre-seed buffer 0 with h(-1) = 0
    if (w == 0 && (l & 1) == 0) {
        const uint32_t off = (uint32_t)(j * 4);            // buf 0
        const uint32_t mof = (uint32_t)(rank * 8);         // mbar[0][rank]
#pragma unroll
        for (int r = 0; r < 8; r++)
            st_async_b64(peer_h[r] + off, 0ull, peer_m[r] + mof);
    }

    uint32_t php[2] = {0u, 0u};    // this warp's parity for mbar[buf][w]

#pragma unroll 1
    for (int t = 0; t < SEQ; t += 2) {
#pragma unroll
        for (int half = 0; half < 2; half++) {
            const int tc = t + half;
            const int p = tc & 1;
            const int q = p ^ 1;
            GruStepState &cur = half ? bufB : bufA;   // also the t+2 refill slot

            // ---- wait ONLY for my source chunk (from CTA w) ----
            wait_parity_cluster(mb + (p * 8 + w) * 8, php[p]);
            php[p] ^= 1u;
            // re-arm this mbar for its next phase (use at tc+2) NOW:
            // guarantees expect_tx precedes any complete_tx of that phase.
            if (l == 0) mbar_arrive_expect_tx(mb + (p * 8 + w) * 8, 128u);

            // ---- matvec over my k-chunk of hbuf[p] ----
            // warp0 seeds accumulators with xr/xz (bias-folded) and bh_n.
            ull ar = 0, az = 0, an = 0;
            if (w == 0) {
                ar = pack2(cur.xr, 0.0f);
                az = pack2(cur.xz, 0.0f);
                an = pack2(bh_n,  0.0f);
            }
            const ull* h2 = (const ull*)(&hbuf[p][32 * w]);
#pragma unroll
            for (int i = 0; i < 16; i++) {
                ull hv = h2[i];
                fma2(ar, wr[i], hv);
                fma2(az, wz[i], hv);
                fma2(an, wn[i], hv);
            }
            // warp0 keeps chunk-0 partials in registers; warps 1-7 STS.
            ull  rz0 = pack2(psum2(ar), psum2(az));
            float pn0 = psum2(an);
            if (w != 0) {
                part_rz[w][l] = rz0;
                part_n[w][l]  = pn0;
            }
            __syncthreads();

            if (w == 0) {
                const float xn = cur.xn;
                // refill with t+2 (LDGs hide under the reduce + gates)
                {
                    int tn = tc + 2 < SEQ ? tc + 2 : tc;
                    const float* xwp = g_xw + tn * HID3;
                    cur.xr = xwp[j]       + bh_r;
                    cur.xz = xwp[256 + j] + bh_z;
                    cur.xn = xwp[512 + j];
                }
                // packed (r,z) reduce + scalar n reduce
                // (same tree as R14: ((0+1)+(2+3))+((4+5)+(6+7)), chunk 0
                //  supplied from registers -> bit-identical)
                ull s01 = add2(rz0,            part_rz[1][l]);
                ull s23 = add2(part_rz[2][l],  part_rz[3][l]);
                ull s45 = add2(part_rz[4][l],  part_rz[5][l]);
                ull s67 = add2(part_rz[6][l],  part_rz[7][l]);
                ull srz = add2(add2(s01, s23), add2(s45, s67));
                float hr, hz; unpack2(srz, hr, hz);   // include xr/xz already
                float hn = ((pn0          + part_n[1][l]) + (part_n[2][l] + part_n[3][l]))
                         + ((part_n[4][l] + part_n[5][l]) + (part_n[6][l] + part_n[7][l]));
                // HW tanh gates: sigm(x) = 0.5*tanh(0.5x) + 0.5
                float rg = fmaf(tanh_hw(0.5f * hr), 0.5f, 0.5f);
                float zg = fmaf(tanh_hw(0.5f * hz), 0.5f, 0.5f);
                float ng = tanh_hw(fmaf(rg, hn, xn));   // hn includes bh_n
                float hnew = fmaf(zg, hprev - ng, ng);
                hprev = hnew;

                // sends: plain f32 from every lane. Skip on the final step.
                if ((tc + 1) < SEQ) {
                    const uint32_t off = (uint32_t)((q * 256 + j) * 4);
                    const uint32_t mof = (uint32_t)((q * 8 + (int)rank) * 8);
#pragma unroll
                    for (int r = 0; r < 8; r++)
                        st_async_f32(peer_h[r] + off, hnew, peer_m[r] + mof);
                }
                z[tc * DIMF + j] = hnew;
            }
        }
    }
    // exit hygiene: no CTA leaves while any peer could still be running
    asm volatile("barrier.cluster.arrive.aligned;" ::: "memory");
    asm volatile("barrier.cluster.wait.aligned;"   ::: "memory");
}

// ---------------------------------------------------------------------------
// Kernel 4: CPC scoring — one block per t
// ---------------------------------------------------------------------------
__global__ __launch_bounds__(256) void cpc_score(
    const float* __restrict__ z, const float* __restrict__ data)
{
    const int bt = blockIdx.x;
    const int t = T_START + bt;
    __shared__ float c[256];
    __shared__ float sims[40];
    __shared__ float wsum[8];
    __shared__ float cn;
    __shared__ float resN[4], resC[4];

    const int tid = threadIdx.x;
    const int w = tid >> 5, l = tid & 31;

    float v = z[t * DIMF + tid];
    c[tid] = v;
    float s = v * v;
#pragma unroll
    for (int off = 16; off > 0; off >>= 1)
        s += __shfl_xor_sync(0xffffffffu, s, off);
    if (l == 0) wsum[w] = s;
    __syncthreads();
    if (tid == 0) {
        float tot = 0;
#pragma unroll
        for (int qq = 0; qq < 8; qq++) tot += wsum[qq];
        cn = fmaxf(sqrtf(tot), 1e-8f);
    }
    __syncthreads();

#pragma unroll
    for (int d = 0; d < 5; d++) {
        int id = w * 5 + d;
        int sp = id / 10 + 1;
        int n = id % 10;
        int row = t + sp + (n ? (NEG_DIST + n - 1) : 0);
        const float* x = data + row * DIMF;
        float dot = 0.0f;
#pragma unroll
        for (int i = 0; i < 8; i++) dot += x[l + 32 * i] * c[l + 32 * i];
#pragma unroll
        for (int off = 16; off > 0; off >>= 1)
            dot += __shfl_xor_sync(0xffffffffu, dot, off);
        if (l == 0) sims[id] = dot / (g_dnorm[row] * cn);
    }
    __syncthreads();

    if (tid < 4) {
        const float* sm = sims + tid * 10;
        float s0 = sm[0];
        float mx = sm[1];
#pragma unroll
        for (int n = 2; n < 10; n++) mx = fmaxf(mx, sm[n]);
        float M = fmaxf(mx, s0);
        float se = 0.0f;
#pragma unroll
        for (int n = 0; n < 10; n++) se += __expf(sm[n] - M);
        resN[tid] = s0 - (M + __logf(se));
        resC[tid] = (s0 >= mx) ? 1.0f : 0.0f;
    }
    __syncthreads();
    if (tid == 0) {
        g_pnce[bt]  = resN[0] + resN[1] + resN[2] + resN[3];
        g_pcorr[bt] = resC[0] + resC[1] + resC[2] + resC[3];
    }
}

// ---------------------------------------------------------------------------
// Kernel 5: final deterministic reduction -> nce, acc
// ---------------------------------------------------------------------------
__global__ __launch_bounds__(256) void cpc_final(float* __restrict__ out)
{
    __shared__ double sN[256], sC[256];
    const int tid = threadIdx.x;
    double a = 0.0, b = 0.0;
    for (int i = tid; i < T_CNT; i += 256) { a += (double)g_pnce[i]; b += (double)g_pcorr[i]; }
    sN[tid] = a; sC[tid] = b;
    __syncthreads();
    for (int s = 128; s > 0; s >>= 1) {
        if (tid < s) { sN[tid] += sN[tid + s]; sC[tid] += sC[tid + s]; }
        __syncthreads();
    }
    if (tid == 0) {
        const double denom = (double)T_CNT * 4.0;
        out[Z_ELEMS]     = (float)(-sN[0] / denom);
        out[Z_ELEMS + 1] = (float)( sC[0] / denom);
    }
}

// ---------------------------------------------------------------------------
extern "C" void kernel_launch(void* const* d_in, const int* in_sizes, int n_in,
                              void* d_out, int out_size)
{
    const float* data = (const float*)d_in[0];
    const float* Wih  = (const float*)d_in[1];
    const float* Whh  = (const float*)d_in[2];
    const float* bih  = (const float*)d_in[3];
    const float* bhh  = (const float*)d_in[4];
    float* out = (float*)d_out;

    dim3 gg(12, 128);
    cpc_xw_gemm<<<gg, 256>>>(data, Wih, bih);   // user launch 1
    cpc_norms<<<SEQ / 8, 256>>>(data);          // user launch 2
    cpc_dummy<<<1, 32>>>();                     // user launch 3
    cpc_gru<<<8, 256>>>(Whh, bhh, out);         // user launch 4 <- capture slot
    cpc_score<<<T_CNT, 256>>>(out, data);
    cpc_final<<<1, 256>>>(out);
}

// round 17
// speedup vs baseline: 1.5051x; 1.0562x over previous
#include <cuda_runtime.h>
#include <cstdint>

// ---------------------------------------------------------------------------
// CPC_80736795230858 : GRU(8192x256, hid 256) + CPC NCE scoring
// ---------------------------------------------------------------------------

#define SEQ      8192
#define DIMF     256
#define HID3     768
#define NEG_DIST 1365          // 8192 // 6
#define T_START  1024          // 8192 // 8
#define T_CNT    5791          // end(6815) - start(1024)
#define Z_ELEMS  (SEQ * DIMF)

typedef unsigned long long ull;

__device__ float g_xw[SEQ * HID3];
__device__ float g_dnorm[SEQ];
__device__ float g_pnce[T_CNT];
__device__ float g_pcorr[T_CNT];

// -------- helpers ----------------------------------------------------------
__device__ __forceinline__ void fma2(ull &acc, ull a, ull b) {
    asm("fma.rn.f32x2 %0, %1, %2, %0;" : "+l"(acc) : "l"(a), "l"(b));
}
__device__ __forceinline__ ull add2(ull a, ull b) {
    ull o; asm("add.rn.f32x2 %0, %1, %2;" : "=l"(o) : "l"(a), "l"(b)); return o;
}
__device__ __forceinline__ ull pack2(float lo, float hi) {
    ull o; asm("mov.b64 %0, {%1, %2};" : "=l"(o) : "f"(lo), "f"(hi)); return o;
}
__device__ __forceinline__ void unpack2(ull a, float &lo, float &hi) {
    asm("mov.b64 {%0,%1}, %2;" : "=f"(lo), "=f"(hi) : "l"(a));
}
__device__ __forceinline__ float psum2(ull a) {
    float lo, hi; unpack2(a, lo, hi); return lo + hi;
}
// HW tanh (sm_75+ MUFU): single op, lat ~16. max rel err ~2^-11.
__device__ __forceinline__ float tanh_hw(float x) {
    float y; asm("tanh.approx.f32 %0, %1;" : "=f"(y) : "f"(x)); return y;
}
__device__ __forceinline__ uint32_t mapa_u32(uint32_t addr, uint32_t rank) {
    uint32_t d;
    asm("mapa.shared::cluster.u32 %0, %1, %2;" : "=r"(d) : "r"(addr), "r"(rank));
    return d;
}
__device__ __forceinline__ void mbar_init(uint32_t mbar, uint32_t cnt) {
    asm volatile("mbarrier.init.shared.b64 [%0], %1;" :: "r"(mbar), "r"(cnt) : "memory");
}
__device__ __forceinline__ void mbar_arrive_expect_tx(uint32_t mbar, uint32_t bytes) {
    asm volatile("mbarrier.arrive.expect_tx.shared::cta.b64 _, [%0], %1;"
                 :: "r"(mbar), "r"(bytes) : "memory");
}
__device__ __forceinline__ void st_async_f32(uint32_t raddr, float v, uint32_t rmbar) {
    asm volatile("st.async.shared::cluster.mbarrier::complete_tx::bytes.f32 [%0], %1, [%2];"
                 :: "r"(raddr), "f"(v), "r"(rmbar) : "memory");
}
__device__ __forceinline__ void st_async_b64(uint32_t raddr, ull v, uint32_t rmbar) {
    asm volatile("st.async.shared::cluster.mbarrier::complete_tx::bytes.b64 [%0], %1, [%2];"
                 :: "r"(raddr), "l"(v), "r"(rmbar) : "memory");
}
__device__ __forceinline__ void wait_parity_cluster(uint32_t mbar, uint32_t parity) {
    asm volatile(
        "{\n\t"
        ".reg .pred P;\n\t"
        "WL%=:\n\t"
        "mbarrier.try_wait.parity.acquire.cluster.shared::cta.b64 P, [%0], %1, 0x989680;\n\t"
        "@P bra.uni WD%=;\n\t"
        "bra.uni WL%=;\n\t"
        "WD%=:\n\t"
        "}"
        :: "r"(mbar), "r"(parity) : "memory");
}

// ---------------------------------------------------------------------------
// Kernel 1: xW = data @ Wih^T + bih  (M=8192, N=768, K=256), f32x2 inner loop
// ---------------------------------------------------------------------------
__global__ __launch_bounds__(256) void cpc_xw_gemm(
    const float* __restrict__ A, const float* __restrict__ B,
    const float* __restrict__ bias)
{
    __shared__ float sA[16][66];     // stride 66 (even) -> 8B-aligned pairs
    __shared__ float sB[16][66];
    const int bx = blockIdx.x, by = blockIdx.y;
    const int tid = threadIdx.x;
    const int tx = tid & 15, ty = tid >> 4;

    ull acc2[4][2];
#pragma unroll
    for (int i = 0; i < 4; i++) { acc2[i][0] = 0; acc2[i][1] = 0; }

    const int lrow = tid >> 2;
    const int lkc  = (tid & 3) * 4;

    for (int k0 = 0; k0 < DIMF; k0 += 16) {
        float4 va = *(const float4*)(A + (by * 64 + lrow) * DIMF + k0 + lkc);
        float4 vb = *(const float4*)(B + (bx * 64 + lrow) * DIMF + k0 + lkc);
        sA[lkc + 0][lrow] = va.x; sA[lkc + 1][lrow] = va.y;
        sA[lkc + 2][lrow] = va.z; sA[lkc + 3][lrow] = va.w;
        sB[lkc + 0][lrow] = vb.x; sB[lkc + 1][lrow] = vb.y;
        sB[lkc + 2][lrow] = vb.z; sB[lkc + 3][lrow] = vb.w;
        __syncthreads();
#pragma unroll
        for (int kk = 0; kk < 16; kk++) {
            ull b2[2];
            b2[0] = *(const ull*)&sB[kk][tx * 4];
            b2[1] = *(const ull*)&sB[kk][tx * 4 + 2];
#pragma unroll
            for (int i = 0; i < 4; i++) {
                float av = sA[kk][ty * 4 + i];
                ull a2 = pack2(av, av);
                fma2(acc2[i][0], a2, b2[0]);
                fma2(acc2[i][1], a2, b2[1]);
            }
        }
        __syncthreads();
    }
#pragma unroll
    for (int i = 0; i < 4; i++) {
        int m = by * 64 + ty * 4 + i;
        float c0, c1, c2, c3;
        unpack2(acc2[i][0], c0, c1);
        unpack2(acc2[i][1], c2, c3);
        int n = bx * 64 + tx * 4;
        g_xw[m * HID3 + n + 0] = c0 + bias[n + 0];
        g_xw[m * HID3 + n + 1] = c1 + bias[n + 1];
        g_xw[m * HID3 + n + 2] = c2 + bias[n + 2];
        g_xw[m * HID3 + n + 3] = c3 + bias[n + 3];
    }
}

// ---------------------------------------------------------------------------
// Kernel 2: row norms of data
// ---------------------------------------------------------------------------
__global__ __launch_bounds__(256) void cpc_norms(const float* __restrict__ data)
{
    int row = blockIdx.x * 8 + (threadIdx.x >> 5);
    int l = threadIdx.x & 31;
    const float4* p = (const float4*)(data + row * DIMF);
    float s = 0.0f;
#pragma unroll
    for (int i = l; i < 64; i += 32) {
        float4 v = p[i];
        s += v.x * v.x + v.y * v.y + v.z * v.z + v.w * v.w;
    }
#pragma unroll
    for (int off = 16; off > 0; off >>= 1)
        s += __shfl_xor_sync(0xffffffffu, s, off);
    if (l == 0) g_dnorm[row] = fmaxf(sqrtf(s), 1e-8f);
}

// ---------------------------------------------------------------------------
// Kernel 2b: ONE dummy — capture slot = 4th user launch => cpc_gru
// ---------------------------------------------------------------------------
__global__ void cpc_dummy() {}

// ---------------------------------------------------------------------------
// Kernel 3: GRU recurrence — 8-CTA cluster, Whh register-resident,
// per-source mbarriers mbar[buf][src] (expect_tx = 128B); warp0-only tail.
// R14 architecture + R17: RANK-ROTATED send order ((rank+i)&7) — self-
// delivery first, every sender->receiver->sender two-cycle costs exactly 8
// issue slots (fixed order costs up to 14), no CTA is systematically last.
// Tail: HW tanh.approx gates, xr/xz/bh_n seeded into matvec accumulators,
// hprev register, plain f32 sends.
// Protocol invariants (R9): arm-after-wait; final-step sends skipped;
// trailing cluster barrier.
// ---------------------------------------------------------------------------
struct GruStepState {
    float xr, xz, xn;      // xr,xz have bhh folded; xn is raw xW value
};

__global__ void __cluster_dims__(8, 1, 1) __launch_bounds__(256, 1)
cpc_gru(const float* __restrict__ Whh,
        const float* __restrict__ bhh,
        float* __restrict__ z)
{
    __shared__ float hbuf[2][256];
    __shared__ ull   part_rz[8][32];       // packed (r,z) partials
    __shared__ float part_n[8][32];
    __shared__ alignas(16) ull mbar[16];   // [buf*8 + src]

    const int tid = threadIdx.x;
    const int w = tid >> 5, l = tid & 31;
    uint32_t rank;
    asm("mov.u32 %0, %%cluster_ctarank;" : "=r"(rank));
    const int j = (int)rank * 32 + l;

    ull wr[16], wz[16], wn[16];
    {
        const ull* pr = (const ull*)(Whh + (j      ) * DIMF + 32 * w);
        const ull* pz = (const ull*)(Whh + (256 + j) * DIMF + 32 * w);
        const ull* pn = (const ull*)(Whh + (512 + j) * DIMF + 32 * w);
#pragma unroll
        for (int i = 0; i < 16; i++) { wr[i] = pr[i]; wz[i] = pz[i]; wn[i] = pn[i]; }
    }

    const uint32_t hb = (uint32_t)__cvta_generic_to_shared(&hbuf[0][0]);
    const uint32_t mb = (uint32_t)__cvta_generic_to_shared(&mbar[0]);

    float bh_r = 0, bh_z = 0, bh_n = 0;
    GruStepState bufA = {0,0,0}, bufB = {0,0,0};
    float hprev = 0.0f;                    // warp0: h(t-1)[j] register copy
    uint32_t peer_h[8], peer_m[8];         // index i => rank (rank+i)&7
    if (w == 0) {
        bh_r = bhh[j]; bh_z = bhh[256 + j]; bh_n = bhh[512 + j];
        bufA.xr = g_xw[j]            + bh_r;    // t = 0
        bufA.xz = g_xw[256 + j]      + bh_z;
        bufA.xn = g_xw[512 + j];                // raw (bh_n NOT folded)
        bufB.xr = g_xw[HID3 + j]       + bh_r;  // t = 1
        bufB.xz = g_xw[HID3 + 256 + j] + bh_z;
        bufB.xn = g_xw[HID3 + 512 + j];
#pragma unroll
        for (int i = 0; i < 8; i++) {
            uint32_t rr = (rank + (uint32_t)i) & 7u;   // rotated destination
            peer_h[i] = mapa_u32(hb, rr);
            peer_m[i] = mapa_u32(mb, rr);
        }
    }
    if (tid < 16) {
        mbar_init(mb + tid * 8, 1);
    }
    ((float*)hbuf)[tid] = 0.0f;
    ((float*)hbuf)[tid + 256] = 0.0f;
    __syncthreads();
    // Arm BOTH buffers' mbars before any cluster traffic is possible.
    if (tid < 16) mbar_arrive_expect_tx(mb + tid * 8, 128u);
    __syncthreads();
    asm volatile("barrier.cluster.arrive.aligned;" ::: "memory");
    asm volatile("barrier.cluster.wait.aligned;"   ::: "memory");

    // pre-seed buffer 0 with h(-1) = 0
    if (w == 0 && (l & 1) == 0) {
        const uint32_t off = (uint32_t)(j * 4);            // buf 0
        const uint32_t mof = (uint32_t)(rank * 8);         // mbar[0][rank]
#pragma unroll
        for (int i = 0; i < 8; i++)
            st_async_b64(peer_h[i] + off, 0ull, peer_m[i] + mof);
    }

    uint32_t php[2] = {0u, 0u};    // this warp's parity for mbar[buf][w]

#pragma unroll 1
    for (int t = 0; t < SEQ; t += 2) {
#pragma unroll
        for (int half = 0; half < 2; half++) {
            const int tc = t + half;
            const int p = tc & 1;
            const int q = p ^ 1;
            GruStepState &cur = half ? bufB : bufA;   // also the t+2 refill slot

            // ---- wait ONLY for my source chunk (from CTA w) ----
            wait_parity_cluster(mb + (p * 8 + w) * 8, php[p]);
            php[p] ^= 1u;
            // re-arm this mbar for its next phase (use at tc+2) NOW:
            // guarantees expect_tx precedes any complete_tx of that phase.
            if (l == 0) mbar_arrive_expect_tx(mb + (p * 8 + w) * 8, 128u);

            // ---- matvec over my k-chunk of hbuf[p] ----
            // warp0 seeds accumulators with xr/xz (bias-folded) and bh_n.
            ull ar = 0, az = 0, an = 0;
            if (w == 0) {
                ar = pack2(cur.xr, 0.0f);
                az = pack2(cur.xz, 0.0f);
                an = pack2(bh_n,  0.0f);
            }
            const ull* h2 = (const ull*)(&hbuf[p][32 * w]);
#pragma unroll
            for (int i = 0; i < 16; i++) {
                ull hv = h2[i];
                fma2(ar, wr[i], hv);
                fma2(az, wz[i], hv);
                fma2(an, wn[i], hv);
            }
            part_rz[w][l] = pack2(psum2(ar), psum2(az));
            part_n[w][l]  = psum2(an);
            __syncthreads();

            if (w == 0) {
                const float xn = cur.xn;
                // refill with t+2 (LDGs hide under the reduce + gates)
                {
                    int tn = tc + 2 < SEQ ? tc + 2 : tc;
                    const float* xwp = g_xw + tn * HID3;
                    cur.xr = xwp[j]       + bh_r;
                    cur.xz = xwp[256 + j] + bh_z;
                    cur.xn = xwp[512 + j];
                }
                // packed (r,z) reduce + scalar n reduce
                ull s01 = add2(part_rz[0][l], part_rz[1][l]);
                ull s23 = add2(part_rz[2][l], part_rz[3][l]);
                ull s45 = add2(part_rz[4][l], part_rz[5][l]);
                ull s67 = add2(part_rz[6][l], part_rz[7][l]);
                ull srz = add2(add2(s01, s23), add2(s45, s67));
                float hr, hz; unpack2(srz, hr, hz);   // include xr/xz already
                float hn = ((part_n[0][l] + part_n[1][l]) + (part_n[2][l] + part_n[3][l]))
                         + ((part_n[4][l] + part_n[5][l]) + (part_n[6][l] + part_n[7][l]));
                // HW tanh gates: sigm(x) = 0.5*tanh(0.5x) + 0.5
                float rg = fmaf(tanh_hw(0.5f * hr), 0.5f, 0.5f);
                float zg = fmaf(tanh_hw(0.5f * hz), 0.5f, 0.5f);
                float ng = tanh_hw(fmaf(rg, hn, xn));   // hn includes bh_n
                float hnew = fmaf(zg, hprev - ng, ng);
                hprev = hnew;

                // sends: rotated order (self first), plain f32 per lane.
                // Skip on the final step.
                if ((tc + 1) < SEQ) {
                    const uint32_t off = (uint32_t)((q * 256 + j) * 4);
                    const uint32_t mof = (uint32_t)((q * 8 + (int)rank) * 8);
#pragma unroll
                    for (int i = 0; i < 8; i++)
                        st_async_f32(peer_h[i] + off, hnew, peer_m[i] + mof);
                }
                z[tc * DIMF + j] = hnew;
            }
        }
    }
    // exit hygiene: no CTA leaves while any peer could still be running
    asm volatile("barrier.cluster.arrive.aligned;" ::: "memory");
    asm volatile("barrier.cluster.wait.aligned;"   ::: "memory");
}

// ---------------------------------------------------------------------------
// Kernel 4: CPC scoring — one block per t
// ---------------------------------------------------------------------------
__global__ __launch_bounds__(256) void cpc_score(
    const float* __restrict__ z, const float* __restrict__ data)
{
    const int bt = blockIdx.x;
    const int t = T_START + bt;
    __shared__ float c[256];
    __shared__ float sims[40];
    __shared__ float wsum[8];
    __shared__ float cn;
    __shared__ float resN[4], resC[4];

    const int tid = threadIdx.x;
    const int w = tid >> 5, l = tid & 31;

    float v = z[t * DIMF + tid];
    c[tid] = v;
    float s = v * v;
#pragma unroll
    for (int off = 16; off > 0; off >>= 1)
        s += __shfl_xor_sync(0xffffffffu, s, off);
    if (l == 0) wsum[w] = s;
    __syncthreads();
    if (tid == 0) {
        float tot = 0;
#pragma unroll
        for (int qq = 0; qq < 8; qq++) tot += wsum[qq];
        cn = fmaxf(sqrtf(tot), 1e-8f);
    }
    __syncthreads();

#pragma unroll
    for (int d = 0; d < 5; d++) {
        int id = w * 5 + d;
        int sp = id / 10 + 1;
        int n = id % 10;
        int row = t + sp + (n ? (NEG_DIST + n - 1) : 0);
        const float* x = data + row * DIMF;
        float dot = 0.0f;
#pragma unroll
        for (int i = 0; i < 8; i++) dot += x[l + 32 * i] * c[l + 32 * i];
#pragma unroll
        for (int off = 16; off > 0; off >>= 1)
            dot += __shfl_xor_sync(0xffffffffu, dot, off);
        if (l == 0) sims[id] = dot / (g_dnorm[row] * cn);
    }
    __syncthreads();

    if (tid < 4) {
        const float* sm = sims + tid * 10;
        float s0 = sm[0];
        float mx = sm[1];
#pragma unroll
        for (int n = 2; n < 10; n++) mx = fmaxf(mx, sm[n]);
        float M = fmaxf(mx, s0);
        float se = 0.0f;
#pragma unroll
        for (int n = 0; n < 10; n++) se += __expf(sm[n] - M);
        resN[tid] = s0 - (M + __logf(se));
        resC[tid] = (s0 >= mx) ? 1.0f : 0.0f;
    }
    __syncthreads();
    if (tid == 0) {
        g_pnce[bt]  = resN[0] + resN[1] + resN[2] + resN[3];
        g_pcorr[bt] = resC[0] + resC[1] + resC[2] + resC[3];
    }
}

// ---------------------------------------------------------------------------
// Kernel 5: final deterministic reduction -> nce, acc
// ---------------------------------------------------------------------------
__global__ __launch_bounds__(256) void cpc_final(float* __restrict__ out)
{
    __shared__ double sN[256], sC[256];
    const int tid = threadIdx.x;
    double a = 0.0, b = 0.0;
    for (int i = tid; i < T_CNT; i += 256) { a += (double)g_pnce[i]; b += (double)g_pcorr[i]; }
    sN[tid] = a; sC[tid] = b;
    __syncthreads();
    for (int s = 128; s > 0; s >>= 1) {
        if (tid < s) { sN[tid] += sN[tid + s]; sC[tid] += sC[tid + s]; }
        __syncthreads();
    }
    if (tid == 0) {
        const double denom = (double)T_CNT * 4.0;
        out[Z_ELEMS]     = (float)(-sN[0] / denom);
        out[Z_ELEMS + 1] = (float)( sC[0] / denom);
    }
}

// ---------------------------------------------------------------------------
extern "C" void kernel_launch(void* const* d_in, const int* in_sizes, int n_in,
                              void* d_out, int out_size)
{
    const float* data = (const float*)d_in[0];
    const float* Wih  = (const float*)d_in[1];
    const float* Whh  = (const float*)d_in[2];
    const float* bih  = (const float*)d_in[3];
    const float* bhh  = (const float*)d_in[4];
    float* out = (float*)d_out;

    dim3 gg(12, 128);
    cpc_xw_gemm<<<gg, 256>>>(data, Wih, bih);   // user launch 1
    cpc_norms<<<SEQ / 8, 256>>>(data);          // user launch 2
    cpc_dummy<<<1, 32>>>();                     // user launch 3
    cpc_gru<<<8, 256>>>(Whh, bhh, out);         // user launch 4 <- capture slot
    cpc_score<<<T_CNT, 256>>>(out, data);
    cpc_final<<<1, 256>>>(out);
}